// round 13
// baseline (speedup 1.0000x reference)
#include <cuda_runtime.h>
#include <math.h>

#define FRAMES 32
#define FRAME_ELEMS (720*1280)          // 921600
#define TOTAL_ELEMS (FRAMES*FRAME_ELEMS)
#define NB 8192                         // 64KB histograms -> L2-resident
#define SPAN 32                         // bins per epilogue thread (NB/256)
#define TPF 45                          // blocks per frame (5 tiles each)
#define TILES_PER_BLK 5
#define NHIST 45                        // hist blocks (5 tiles each, frame 0)
#define TPB 256
#define NBLK_MAIN (TPF*FRAMES)          // 1440
#define NSIM (TPF*FRAMES)               // 1440 five-tile SIM blocks
#define NSIM_TOTAL (NSIM + NHIST)       // 1485 = 2.007 waves @ occ5 (740 concurrent)

// All fields valid when zero-initialized (mins stored as max of ~encF).
struct Stats {
    double sum_p[FRAMES];
    double sum_p2[FRAMES];
    double sum_fp[FRAMES];
    double cnt_fix[FRAMES];
    double sum_sim[FRAMES];
    double sum_g;
    unsigned pmin_c, gmin_c;     // global mins: stores max(~encF(x))
    unsigned pmax_e;             // global pred max: max(encF(x))
    float simc[4];               // pmin, gmin, invTp, invTg
};

__device__ Stats g_s;            // zero at module load; k_auc re-zeros each call
__device__ unsigned g_hf[NB];
__device__ unsigned g_hn[NB];
__device__ unsigned g_ticket1;   // k_main completion ticket

// ---------- helpers ----------
__device__ __forceinline__ unsigned encF(float x) {
    unsigned u = __float_as_uint(x);
    return (u & 0x80000000u) ? ~u : (u | 0x80000000u);
}
__device__ __forceinline__ float decF(unsigned u) {
    u = (u & 0x80000000u) ? (u & 0x7FFFFFFFu) : ~u;
    return __uint_as_float(u);
}

__device__ __forceinline__ float blkSumF(float v, float* sh) {
    #pragma unroll
    for (int o = 16; o; o >>= 1) v += __shfl_down_sync(0xFFFFFFFFu, v, o);
    if ((threadIdx.x & 31) == 0) sh[threadIdx.x >> 5] = v;
    __syncthreads();
    float r = 0.f;
    if (threadIdx.x < 32) {
        r = (threadIdx.x < 8) ? sh[threadIdx.x] : 0.f;
        #pragma unroll
        for (int o = 4; o; o >>= 1) r += __shfl_down_sync(0xFFFFFFFFu, r, o);
    }
    __syncthreads();
    return r;   // valid on thread 0
}

// ---------- Pass 1: NSS stats + global extrema. 5 tiles/block (at floor, unchanged). ----------
__global__ void __launch_bounds__(TPB, 5) k_main(const float* __restrict__ pred,
                                                 const float* __restrict__ gt,
                                                 const int* __restrict__ fix) {
    __shared__ float sh[64];     // [warp][quantity]
    int f = blockIdx.y;

    float sp = 0.f, sp2 = 0.f, sfp = 0.f, sg = 0.f, cf = 0.f;
    float pmn = 3.4e38f, gmn = 3.4e38f, pmx = -3.4e38f;

    #pragma unroll
    for (int tile = 0; tile < TILES_PER_BLK; tile++) {
        size_t base = (size_t)f * FRAME_ELEMS
                    + ((size_t)blockIdx.x * TILES_PER_BLK + tile) * 4096u;
        const float4* p4 = reinterpret_cast<const float4*>(pred + base);
        const float4* g4 = reinterpret_cast<const float4*>(gt + base);
        const int4*   x4 = reinterpret_cast<const int4*>(fix + base);
        #pragma unroll
        for (int c = 0; c < 2; c++) {
            int i0 = threadIdx.x + c * 512;
            float4 P0 = p4[i0], P1 = p4[i0 + 256];
            float4 G0 = g4[i0], G1 = g4[i0 + 256];
            int4   X0 = x4[i0], X1 = x4[i0 + 256];
            #pragma unroll
            for (int k = 0; k < 2; k++) {
                float4 p = k ? P1 : P0;
                float4 g = k ? G1 : G0;
                int4   x = k ? X1 : X0;
                sp  += (p.x + p.y) + (p.z + p.w);
                sp2 += (p.x*p.x + p.y*p.y) + (p.z*p.z + p.w*p.w);
                sg  += (g.x + g.y) + (g.z + g.w);
                pmn = fminf(pmn, fminf(fminf(p.x, p.y), fminf(p.z, p.w)));
                pmx = fmaxf(pmx, fmaxf(fmaxf(p.x, p.y), fmaxf(p.z, p.w)));
                gmn = fminf(gmn, fminf(fminf(g.x, g.y), fminf(g.z, g.w)));
                if (x.x) { sfp += p.x; cf += 1.f; }
                if (x.y) { sfp += p.y; cf += 1.f; }
                if (x.z) { sfp += p.z; cf += 1.f; }
                if (x.w) { sfp += p.w; cf += 1.f; }
            }
        }
    }

    int lane = threadIdx.x & 31, wid = threadIdx.x >> 5;
    #pragma unroll
    for (int o = 16; o; o >>= 1) {
        sp  += __shfl_down_sync(0xFFFFFFFFu, sp,  o);
        sp2 += __shfl_down_sync(0xFFFFFFFFu, sp2, o);
        sfp += __shfl_down_sync(0xFFFFFFFFu, sfp, o);
        sg  += __shfl_down_sync(0xFFFFFFFFu, sg,  o);
        cf  += __shfl_down_sync(0xFFFFFFFFu, cf,  o);
        pmn = fminf(pmn, __shfl_down_sync(0xFFFFFFFFu, pmn, o));
        gmn = fminf(gmn, __shfl_down_sync(0xFFFFFFFFu, gmn, o));
        pmx = fmaxf(pmx, __shfl_down_sync(0xFFFFFFFFu, pmx, o));
    }
    if (lane == 0) {
        sh[wid * 8 + 0] = sp;  sh[wid * 8 + 1] = sp2;
        sh[wid * 8 + 2] = sfp; sh[wid * 8 + 3] = sg;
        sh[wid * 8 + 4] = cf;  sh[wid * 8 + 5] = pmn;
        sh[wid * 8 + 6] = gmn; sh[wid * 8 + 7] = pmx;
    }
    __syncthreads();
    if (threadIdx.x < 64) {
        int q = threadIdx.x >> 3, w = threadIdx.x & 7;
        float v = sh[w * 8 + q];
        #pragma unroll
        for (int o = 4; o; o >>= 1) {
            float s = __shfl_down_sync(0xFFFFFFFFu, v, o, 8);
            if (q < 5) v += s;
            else if (q == 7) v = fmaxf(v, s);
            else v = fminf(v, s);
        }
        if (w == 0) {
            switch (q) {
                case 0: atomicAdd(&g_s.sum_p[f],   (double)v); break;
                case 1: atomicAdd(&g_s.sum_p2[f],  (double)v); break;
                case 2: atomicAdd(&g_s.sum_fp[f],  (double)v); break;
                case 3: atomicAdd(&g_s.sum_g,      (double)v); break;
                case 4: atomicAdd(&g_s.cnt_fix[f], (double)v); break;
                case 5: atomicMax(&g_s.pmin_c, ~encF(v)); break;
                case 6: atomicMax(&g_s.gmin_c, ~encF(v)); break;
                case 7: atomicMax(&g_s.pmax_e,  encF(v)); break;
            }
            __threadfence();
        }
    }
    __syncthreads();
    if (threadIdx.x == 0) {
        unsigned tk = atomicAdd(&g_ticket1, 1u);
        if (tk == NBLK_MAIN - 1u) {
            float pmin = decF(~g_s.pmin_c);
            float gmin = decF(~g_s.gmin_c);
            double sumP = 0.0;
            #pragma unroll
            for (int ff = 0; ff < FRAMES; ff++) sumP += __ldcg(&g_s.sum_p[ff]);
            double Tp = sumP - (double)TOTAL_ELEMS * (double)pmin;
            double Tg = __ldcg(&g_s.sum_g) - (double)TOTAL_ELEMS * (double)gmin;
            g_s.simc[0] = pmin;
            g_s.simc[1] = gmin;
            g_s.simc[2] = (float)(1.0 / Tp);
            g_s.simc[3] = (float)(1.0 / Tg);
        }
    }
}

// ---------- Pass 2: 45 hist blocks FIRST (wave-1, overlap-hidden), then 1440
//            five-tile SIM blocks. 1485 blocks @ occ5 = 2.007 waves. ----------
__global__ void __launch_bounds__(TPB, 5) k_sim(const float* __restrict__ pred,
                                                const float* __restrict__ gt,
                                                const int* __restrict__ fix) {
    int bid = blockIdx.x;

    if (bid < NHIST) {
        // --- histogram: 5 tiles of frame 0, bins from global extrema ---
        float p0min = decF(~g_s.pmin_c);
        float p0max = decF(g_s.pmax_e);
        float scale = (float)NB / (p0max - p0min);
        #pragma unroll
        for (int tile = 0; tile < TILES_PER_BLK; tile++) {
            size_t base = ((size_t)bid * TILES_PER_BLK + tile) * 4096u;
            const float4* p4 = reinterpret_cast<const float4*>(pred + base);
            const int4*   x4 = reinterpret_cast<const int4*>(fix + base);
            #pragma unroll
            for (int c = 0; c < 2; c++) {
                int i0 = threadIdx.x + c * 512;
                float4 P0 = p4[i0], P1 = p4[i0 + 256];
                int4   X0 = x4[i0], X1 = x4[i0 + 256];
                #pragma unroll
                for (int k = 0; k < 2; k++) {
                    float4 p = k ? P1 : P0;
                    int4   x = k ? X1 : X0;
                    int b0 = min(NB - 1, (int)((p.x - p0min) * scale));
                    int b1 = min(NB - 1, (int)((p.y - p0min) * scale));
                    int b2 = min(NB - 1, (int)((p.z - p0min) * scale));
                    int b3 = min(NB - 1, (int)((p.w - p0min) * scale));
                    atomicAdd(x.x ? &g_hf[b0] : &g_hn[b0], 1u);
                    atomicAdd(x.y ? &g_hf[b1] : &g_hn[b1], 1u);
                    atomicAdd(x.z ? &g_hf[b2] : &g_hn[b2], 1u);
                    atomicAdd(x.w ? &g_hf[b3] : &g_hn[b3], 1u);
                }
            }
        }
        return;
    }

    // --- SIM path: 5 tiles/block, reversed so processing ends on frame 0 ---
    __shared__ float shf[8];
    int ridx = (NSIM - 1) - (bid - NHIST);   // 1439..0
    int f    = ridx / TPF;
    int xb   = ridx % TPF;

    float pmin = g_s.simc[0], gmin = g_s.simc[1];
    float ip   = g_s.simc[2], ig   = g_s.simc[3];

    float acc = 0.f;
    #pragma unroll
    for (int tile = 0; tile < TILES_PER_BLK; tile++) {
        size_t base = (size_t)f * FRAME_ELEMS
                    + ((size_t)xb * TILES_PER_BLK + tile) * 4096u;
        const float4* p4 = reinterpret_cast<const float4*>(pred + base);
        const float4* g4 = reinterpret_cast<const float4*>(gt + base);
        #pragma unroll
        for (int c = 0; c < 2; c++) {
            int i0 = threadIdx.x + c * 512;
            float4 P0 = p4[i0], P1 = p4[i0 + 256];
            float4 G0 = g4[i0], G1 = g4[i0 + 256];
            #pragma unroll
            for (int k = 0; k < 2; k++) {
                float4 p = k ? P1 : P0;
                float4 g = k ? G1 : G0;
                if (g.x > gmin) acc += fminf((g.x - gmin) * ig, (p.x - pmin) * ip);
                if (g.y > gmin) acc += fminf((g.y - gmin) * ig, (p.y - pmin) * ip);
                if (g.z > gmin) acc += fminf((g.z - gmin) * ig, (p.z - pmin) * ip);
                if (g.w > gmin) acc += fminf((g.w - gmin) * ig, (p.w - pmin) * ip);
            }
        }
    }
    float r = blkSumF(acc, shf);
    if (threadIdx.x == 0) atomicAdd(&g_s.sum_sim[f], (double)r);
}

// ---------- Pass 3: single-block epilogue (hist complete via kernel boundary, L2-hot) ----------
__global__ void __launch_bounds__(TPB) k_auc(float* __restrict__ out) {
    int t = threadIdx.x;
    __shared__ unsigned swt[8];
    __shared__ unsigned long long sU[3];
    __shared__ int sB;
    int lane = t & 31, wid = t >> 5;
    if (t == 0) { sB = NB; sU[0] = 0ull; sU[1] = 0ull; sU[2] = 0ull; }
    __syncthreads();

    // batch ALL histogram loads upfront (one round-trip, L2-hot)
    unsigned hf[SPAN], hn[SPAN];
    {
        const uint4* hf4 = reinterpret_cast<const uint4*>(g_hf) + t * (SPAN / 4);
        const uint4* hn4 = reinterpret_cast<const uint4*>(g_hn) + t * (SPAN / 4);
        #pragma unroll
        for (int i = 0; i < SPAN / 4; i++) {
            uint4 a = __ldcg(&hf4[i]);
            uint4 b = __ldcg(&hn4[i]);
            hf[4*i] = a.x; hf[4*i+1] = a.y; hf[4*i+2] = a.z; hf[4*i+3] = a.w;
            hn[4*i] = b.x; hn[4*i+1] = b.y; hn[4*i+2] = b.z; hn[4*i+3] = b.w;
        }
    }
    int base = t * SPAN;

    unsigned sumF = 0;
    #pragma unroll
    for (int i = 0; i < SPAN; i++) sumF += hf[i];

    unsigned incl = sumF;
    #pragma unroll
    for (int o = 1; o < 32; o <<= 1) {
        unsigned v = __shfl_up_sync(0xFFFFFFFFu, incl, o);
        if (lane >= o) incl += v;
    }
    if (lane == 31) swt[wid] = incl;

    int mn = NB;
    #pragma unroll
    for (int i = 0; i < SPAN; i++) if (hf[i] && base + i < mn) mn = base + i;
    #pragma unroll
    for (int o = 16; o; o >>= 1) mn = min(mn, __shfl_down_sync(0xFFFFFFFFu, mn, o));
    __syncthreads();
    if (lane == 0) atomicMin(&sB, mn);
    if (t < 8) {
        unsigned w = swt[t];
        unsigned s = w;
        #pragma unroll
        for (int o = 1; o < 8; o <<= 1) {
            unsigned v = __shfl_up_sync(0xFFu, s, o);
            if (t >= o) s += v;
        }
        swt[t] = s - w;
    }
    __syncthreads();
    unsigned F = swt[wid] + (incl - sumF);
    int bstar = sB;

    unsigned long long u1 = 0, u2 = 0, u3 = 0;
    #pragma unroll
    for (int i = 0; i < SPAN; i++) {
        u1 += (unsigned long long)hn[i] * F;
        u2 += (unsigned long long)hf[i] * hn[i];
        if (base + i > bstar) u3 += hn[i];
        F += hf[i];
    }
    #pragma unroll
    for (int o = 16; o; o >>= 1) {
        u1 += __shfl_down_sync(0xFFFFFFFFu, u1, o);
        u2 += __shfl_down_sync(0xFFFFFFFFu, u2, o);
        u3 += __shfl_down_sync(0xFFFFFFFFu, u3, o);
    }
    if (lane == 0) {
        atomicAdd(&sU[0], u1);
        atomicAdd(&sU[1], u2);
        atomicAdd(&sU[2], u3);
    }
    __syncthreads();

    if (wid == 0) {
        double Np = (double)FRAME_ELEMS;
        double m   = __ldcg(&g_s.sum_p[lane]) / Np;
        double var = __ldcg(&g_s.sum_p2[lane]) / Np - m * m;
        double sd  = sqrt(var);
        double c   = __ldcg(&g_s.cnt_fix[lane]);
        double nssf = (__ldcg(&g_s.sum_fp[lane]) - c * m) / (sd * c);
        double simf = __ldcg(&g_s.sum_sim[lane]);
        double Nf0 = __shfl_sync(0xFFFFFFFFu, c, 0);
        #pragma unroll
        for (int o = 16; o; o >>= 1) {
            nssf += __shfl_down_sync(0xFFFFFFFFu, nssf, o);
            simf += __shfl_down_sync(0xFFFFFFFFu, simf, o);
        }
        if (lane == 0) {
            double Nf = Nf0;
            double D  = Np - Nf;
            double S  = (double)sU[0] + 0.5 * (double)sU[1];
            double b  = (double)sU[2];
            double auc = ((2.0 * Nf + 1.0) * b + 1.0 - 2.0 * S) / (2.0 * Nf * D)
                       + 1.0 - (b + 1.0) / D;
            double sim = simf / (double)FRAMES;
            double nss = nssf / (double)FRAMES;
            double loss = auc + sim + nss;
            out[0] = (float)loss;
            out[1] = (float)auc;
            out[2] = (float)sim;
            out[3] = (float)nss;
        }
    }

    // ---- self-clean device state for the next graph replay ----
    __syncthreads();
    {
        uint4* hf4w = reinterpret_cast<uint4*>(g_hf) + t * (SPAN / 4);
        uint4* hn4w = reinterpret_cast<uint4*>(g_hn) + t * (SPAN / 4);
        uint4 z = make_uint4(0, 0, 0, 0);
        #pragma unroll
        for (int i = 0; i < SPAN / 4; i++) { hf4w[i] = z; hn4w[i] = z; }
        unsigned long long* s8 = reinterpret_cast<unsigned long long*>(&g_s);
        int n8 = (int)(sizeof(Stats) / 8);
        if (t < n8) s8[t] = 0ull;
        if (t == 0) {
            char* sc8 = reinterpret_cast<char*>(&g_s);
            for (int i = n8 * 8; i < (int)sizeof(Stats); i++) sc8[i] = 0;
            g_ticket1 = 0u;
        }
    }
}

extern "C" void kernel_launch(void* const* d_in, const int* in_sizes, int n_in,
                              void* d_out, int out_size) {
    const float* pred = (const float*)d_in[0];
    const float* gt   = (const float*)d_in[1];
    const int*   fix  = (const int*)d_in[2];
    float* out = (float*)d_out;

    dim3 gmain(TPF, FRAMES);            // 1440 blocks, 5 tiles each
    k_main<<<gmain, TPB>>>(pred, gt, fix);
    k_sim<<<NSIM_TOTAL, TPB>>>(pred, gt, fix);   // 45 hist first + 1440 5-tile SIM
    k_auc<<<1, TPB>>>(out);
}

// round 14
// speedup vs baseline: 1.1527x; 1.1527x over previous
#include <cuda_runtime.h>
#include <math.h>

#define FRAMES 32
#define FRAME_ELEMS (720*1280)          // 921600
#define TOTAL_ELEMS (FRAMES*FRAME_ELEMS)
#define NB 8192                         // 64KB histograms -> L2-resident
#define SPAN 32                         // bins per epilogue thread (NB/256)
#define TPF 45                          // k_main blocks per frame (5 tiles each)
#define TILES_PER_BLK 5
#define SPF 225                         // SIM tiles per frame
#define NHIST 45                        // hist blocks (5 tiles each, frame 0)
#define TPB 256
#define NBLK_MAIN (TPF*FRAMES)          // 1440
#define NSIM (SPF*FRAMES)               // 7200 fine SIM blocks
#define NSIM_TOTAL (NSIM + NHIST)       // 7245

// All fields valid when zero-initialized (mins stored as max of ~encF).
struct Stats {
    double sum_p[FRAMES];
    double sum_p2[FRAMES];
    double sum_fp[FRAMES];
    double cnt_fix[FRAMES];
    double sum_sim[FRAMES];
    double sum_g;
    unsigned pmin_c, gmin_c;     // global mins: stores max(~encF(x))
    unsigned pmax_e;             // global pred max: max(encF(x))
    float simc[4];               // pmin, gmin, invTp, invTg
};

__device__ Stats g_s;            // zero at module load; k_auc re-zeros each call
__device__ unsigned g_hf[NB];
__device__ unsigned g_hn[NB];
__device__ unsigned g_ticket1;   // k_main completion ticket

// ---------- helpers ----------
__device__ __forceinline__ unsigned encF(float x) {
    unsigned u = __float_as_uint(x);
    return (u & 0x80000000u) ? ~u : (u | 0x80000000u);
}
__device__ __forceinline__ float decF(unsigned u) {
    u = (u & 0x80000000u) ? (u & 0x7FFFFFFFu) : ~u;
    return __uint_as_float(u);
}

__device__ __forceinline__ float blkSumF(float v, float* sh) {
    #pragma unroll
    for (int o = 16; o; o >>= 1) v += __shfl_down_sync(0xFFFFFFFFu, v, o);
    if ((threadIdx.x & 31) == 0) sh[threadIdx.x >> 5] = v;
    __syncthreads();
    float r = 0.f;
    if (threadIdx.x < 32) {
        r = (threadIdx.x < 8) ? sh[threadIdx.x] : 0.f;
        #pragma unroll
        for (int o = 4; o; o >>= 1) r += __shfl_down_sync(0xFFFFFFFFu, r, o);
    }
    __syncthreads();
    return r;   // valid on thread 0
}

// ---------- Pass 1: NSS stats + global extrema. 5 tiles/block (at floor). ----------
__global__ void __launch_bounds__(TPB, 5) k_main(const float* __restrict__ pred,
                                                 const float* __restrict__ gt,
                                                 const int* __restrict__ fix) {
    __shared__ float sh[64];     // [warp][quantity]
    int f = blockIdx.y;

    float sp = 0.f, sp2 = 0.f, sfp = 0.f, sg = 0.f, cf = 0.f;
    float pmn = 3.4e38f, gmn = 3.4e38f, pmx = -3.4e38f;

    #pragma unroll
    for (int tile = 0; tile < TILES_PER_BLK; tile++) {
        size_t base = (size_t)f * FRAME_ELEMS
                    + ((size_t)blockIdx.x * TILES_PER_BLK + tile) * 4096u;
        const float4* p4 = reinterpret_cast<const float4*>(pred + base);
        const float4* g4 = reinterpret_cast<const float4*>(gt + base);
        const int4*   x4 = reinterpret_cast<const int4*>(fix + base);
        #pragma unroll
        for (int c = 0; c < 2; c++) {
            int i0 = threadIdx.x + c * 512;
            float4 P0 = p4[i0], P1 = p4[i0 + 256];
            float4 G0 = g4[i0], G1 = g4[i0 + 256];
            int4   X0 = __ldcs(&x4[i0]);           // streaming: fix never re-read
            int4   X1 = __ldcs(&x4[i0 + 256]);
            #pragma unroll
            for (int k = 0; k < 2; k++) {
                float4 p = k ? P1 : P0;
                float4 g = k ? G1 : G0;
                int4   x = k ? X1 : X0;
                sp  += (p.x + p.y) + (p.z + p.w);
                sp2 += (p.x*p.x + p.y*p.y) + (p.z*p.z + p.w*p.w);
                sg  += (g.x + g.y) + (g.z + g.w);
                pmn = fminf(pmn, fminf(fminf(p.x, p.y), fminf(p.z, p.w)));
                pmx = fmaxf(pmx, fmaxf(fmaxf(p.x, p.y), fmaxf(p.z, p.w)));
                gmn = fminf(gmn, fminf(fminf(g.x, g.y), fminf(g.z, g.w)));
                if (x.x) { sfp += p.x; cf += 1.f; }
                if (x.y) { sfp += p.y; cf += 1.f; }
                if (x.z) { sfp += p.z; cf += 1.f; }
                if (x.w) { sfp += p.w; cf += 1.f; }
            }
        }
    }

    int lane = threadIdx.x & 31, wid = threadIdx.x >> 5;
    #pragma unroll
    for (int o = 16; o; o >>= 1) {
        sp  += __shfl_down_sync(0xFFFFFFFFu, sp,  o);
        sp2 += __shfl_down_sync(0xFFFFFFFFu, sp2, o);
        sfp += __shfl_down_sync(0xFFFFFFFFu, sfp, o);
        sg  += __shfl_down_sync(0xFFFFFFFFu, sg,  o);
        cf  += __shfl_down_sync(0xFFFFFFFFu, cf,  o);
        pmn = fminf(pmn, __shfl_down_sync(0xFFFFFFFFu, pmn, o));
        gmn = fminf(gmn, __shfl_down_sync(0xFFFFFFFFu, gmn, o));
        pmx = fmaxf(pmx, __shfl_down_sync(0xFFFFFFFFu, pmx, o));
    }
    if (lane == 0) {
        sh[wid * 8 + 0] = sp;  sh[wid * 8 + 1] = sp2;
        sh[wid * 8 + 2] = sfp; sh[wid * 8 + 3] = sg;
        sh[wid * 8 + 4] = cf;  sh[wid * 8 + 5] = pmn;
        sh[wid * 8 + 6] = gmn; sh[wid * 8 + 7] = pmx;
    }
    __syncthreads();
    if (threadIdx.x < 64) {
        int q = threadIdx.x >> 3, w = threadIdx.x & 7;
        float v = sh[w * 8 + q];
        #pragma unroll
        for (int o = 4; o; o >>= 1) {
            float s = __shfl_down_sync(0xFFFFFFFFu, v, o, 8);
            if (q < 5) v += s;
            else if (q == 7) v = fmaxf(v, s);
            else v = fminf(v, s);
        }
        if (w == 0) {
            switch (q) {
                case 0: atomicAdd(&g_s.sum_p[f],   (double)v); break;
                case 1: atomicAdd(&g_s.sum_p2[f],  (double)v); break;
                case 2: atomicAdd(&g_s.sum_fp[f],  (double)v); break;
                case 3: atomicAdd(&g_s.sum_g,      (double)v); break;
                case 4: atomicAdd(&g_s.cnt_fix[f], (double)v); break;
                case 5: atomicMax(&g_s.pmin_c, ~encF(v)); break;
                case 6: atomicMax(&g_s.gmin_c, ~encF(v)); break;
                case 7: atomicMax(&g_s.pmax_e,  encF(v)); break;
            }
            __threadfence();
        }
    }
    __syncthreads();
    if (threadIdx.x == 0) {
        unsigned tk = atomicAdd(&g_ticket1, 1u);
        if (tk == NBLK_MAIN - 1u) {
            float pmin = decF(~g_s.pmin_c);
            float gmin = decF(~g_s.gmin_c);
            double sumP = 0.0;
            #pragma unroll
            for (int ff = 0; ff < FRAMES; ff++) sumP += __ldcg(&g_s.sum_p[ff]);
            double Tp = sumP - (double)TOTAL_ELEMS * (double)pmin;
            double Tg = __ldcg(&g_s.sum_g) - (double)TOTAL_ELEMS * (double)gmin;
            g_s.simc[0] = pmin;
            g_s.simc[1] = gmin;
            g_s.simc[2] = (float)(1.0 / Tp);
            g_s.simc[3] = (float)(1.0 / Tg);
        }
    }
}

// ---------- Pass 2: first NHIST blocks = frame-0 histogram (wave-1, overlap-hidden);
//            remaining 7200 = fine-grained SIM blocks (measured-best shape). ----------
__global__ void __launch_bounds__(TPB, 6) k_sim(const float* __restrict__ pred,
                                                const float* __restrict__ gt,
                                                const int* __restrict__ fix) {
    int bid = blockIdx.x;

    if (bid < NHIST) {
        // --- histogram: 5 tiles of frame 0, bins from global extrema ---
        float p0min = decF(~g_s.pmin_c);
        float p0max = decF(g_s.pmax_e);
        float scale = (float)NB / (p0max - p0min);
        #pragma unroll
        for (int tile = 0; tile < TILES_PER_BLK; tile++) {
            size_t base = ((size_t)bid * TILES_PER_BLK + tile) * 4096u;
            const float4* p4 = reinterpret_cast<const float4*>(pred + base);
            const int4*   x4 = reinterpret_cast<const int4*>(fix + base);
            #pragma unroll
            for (int c = 0; c < 2; c++) {
                int i0 = threadIdx.x + c * 512;
                float4 P0 = p4[i0], P1 = p4[i0 + 256];
                int4   X0 = __ldcs(&x4[i0]), X1 = __ldcs(&x4[i0 + 256]);
                #pragma unroll
                for (int k = 0; k < 2; k++) {
                    float4 p = k ? P1 : P0;
                    int4   x = k ? X1 : X0;
                    int b0 = min(NB - 1, (int)((p.x - p0min) * scale));
                    int b1 = min(NB - 1, (int)((p.y - p0min) * scale));
                    int b2 = min(NB - 1, (int)((p.z - p0min) * scale));
                    int b3 = min(NB - 1, (int)((p.w - p0min) * scale));
                    atomicAdd(x.x ? &g_hf[b0] : &g_hn[b0], 1u);
                    atomicAdd(x.y ? &g_hf[b1] : &g_hn[b1], 1u);
                    atomicAdd(x.z ? &g_hf[b2] : &g_hn[b2], 1u);
                    atomicAdd(x.w ? &g_hf[b3] : &g_hn[b3], 1u);
                }
            }
        }
        return;
    }

    // --- SIM path: tile index reversed so processing ends on frame 0 ---
    __shared__ float shf[8];
    int idx = (NSIM - 1) - (bid - NHIST);    // 7199..0
    int f   = idx / SPF;
    int xb  = idx % SPF;
    size_t base = (size_t)f * FRAME_ELEMS + (size_t)xb * 4096u;
    const float4* p4 = reinterpret_cast<const float4*>(pred + base);
    const float4* g4 = reinterpret_cast<const float4*>(gt + base);

    float pmin = g_s.simc[0], gmin = g_s.simc[1];
    float ip   = g_s.simc[2], ig   = g_s.simc[3];

    float acc = 0.f;
    #pragma unroll
    for (int c = 0; c < 2; c++) {
        int i0 = threadIdx.x + c * 512;
        float4 P0 = p4[i0], P1 = p4[i0 + 256];
        float4 G0 = __ldcs(&g4[i0]), G1 = __ldcs(&g4[i0 + 256]);   // gt: last use
        #pragma unroll
        for (int k = 0; k < 2; k++) {
            float4 p = k ? P1 : P0;
            float4 g = k ? G1 : G0;
            if (g.x > gmin) acc += fminf((g.x - gmin) * ig, (p.x - pmin) * ip);
            if (g.y > gmin) acc += fminf((g.y - gmin) * ig, (p.y - pmin) * ip);
            if (g.z > gmin) acc += fminf((g.z - gmin) * ig, (p.z - pmin) * ip);
            if (g.w > gmin) acc += fminf((g.w - gmin) * ig, (p.w - pmin) * ip);
        }
    }
    float r = blkSumF(acc, shf);
    if (threadIdx.x == 0) atomicAdd(&g_s.sum_sim[f], (double)r);
}

// ---------- Pass 3: single-block epilogue (hist complete via kernel boundary, L2-hot) ----------
__global__ void __launch_bounds__(TPB) k_auc(float* __restrict__ out) {
    int t = threadIdx.x;
    __shared__ unsigned swt[8];
    __shared__ unsigned long long sU[3];
    __shared__ int sB;
    int lane = t & 31, wid = t >> 5;
    if (t == 0) { sB = NB; sU[0] = 0ull; sU[1] = 0ull; sU[2] = 0ull; }
    __syncthreads();

    // batch ALL histogram loads upfront (one round-trip, L2-hot)
    unsigned hf[SPAN], hn[SPAN];
    {
        const uint4* hf4 = reinterpret_cast<const uint4*>(g_hf) + t * (SPAN / 4);
        const uint4* hn4 = reinterpret_cast<const uint4*>(g_hn) + t * (SPAN / 4);
        #pragma unroll
        for (int i = 0; i < SPAN / 4; i++) {
            uint4 a = __ldcg(&hf4[i]);
            uint4 b = __ldcg(&hn4[i]);
            hf[4*i] = a.x; hf[4*i+1] = a.y; hf[4*i+2] = a.z; hf[4*i+3] = a.w;
            hn[4*i] = b.x; hn[4*i+1] = b.y; hn[4*i+2] = b.z; hn[4*i+3] = b.w;
        }
    }
    int base = t * SPAN;

    unsigned sumF = 0;
    #pragma unroll
    for (int i = 0; i < SPAN; i++) sumF += hf[i];

    unsigned incl = sumF;
    #pragma unroll
    for (int o = 1; o < 32; o <<= 1) {
        unsigned v = __shfl_up_sync(0xFFFFFFFFu, incl, o);
        if (lane >= o) incl += v;
    }
    if (lane == 31) swt[wid] = incl;

    int mn = NB;
    #pragma unroll
    for (int i = 0; i < SPAN; i++) if (hf[i] && base + i < mn) mn = base + i;
    #pragma unroll
    for (int o = 16; o; o >>= 1) mn = min(mn, __shfl_down_sync(0xFFFFFFFFu, mn, o));
    __syncthreads();
    if (lane == 0) atomicMin(&sB, mn);
    if (t < 8) {
        unsigned w = swt[t];
        unsigned s = w;
        #pragma unroll
        for (int o = 1; o < 8; o <<= 1) {
            unsigned v = __shfl_up_sync(0xFFu, s, o);
            if (t >= o) s += v;
        }
        swt[t] = s - w;
    }
    __syncthreads();
    unsigned F = swt[wid] + (incl - sumF);
    int bstar = sB;

    unsigned long long u1 = 0, u2 = 0, u3 = 0;
    #pragma unroll
    for (int i = 0; i < SPAN; i++) {
        u1 += (unsigned long long)hn[i] * F;
        u2 += (unsigned long long)hf[i] * hn[i];
        if (base + i > bstar) u3 += hn[i];
        F += hf[i];
    }
    #pragma unroll
    for (int o = 16; o; o >>= 1) {
        u1 += __shfl_down_sync(0xFFFFFFFFu, u1, o);
        u2 += __shfl_down_sync(0xFFFFFFFFu, u2, o);
        u3 += __shfl_down_sync(0xFFFFFFFFu, u3, o);
    }
    if (lane == 0) {
        atomicAdd(&sU[0], u1);
        atomicAdd(&sU[1], u2);
        atomicAdd(&sU[2], u3);
    }
    __syncthreads();

    if (wid == 0) {
        double Np = (double)FRAME_ELEMS;
        double m   = __ldcg(&g_s.sum_p[lane]) / Np;
        double var = __ldcg(&g_s.sum_p2[lane]) / Np - m * m;
        double sd  = sqrt(var);
        double c   = __ldcg(&g_s.cnt_fix[lane]);
        double nssf = (__ldcg(&g_s.sum_fp[lane]) - c * m) / (sd * c);
        double simf = __ldcg(&g_s.sum_sim[lane]);
        double Nf0 = __shfl_sync(0xFFFFFFFFu, c, 0);
        #pragma unroll
        for (int o = 16; o; o >>= 1) {
            nssf += __shfl_down_sync(0xFFFFFFFFu, nssf, o);
            simf += __shfl_down_sync(0xFFFFFFFFu, simf, o);
        }
        if (lane == 0) {
            double Nf = Nf0;
            double D  = Np - Nf;
            double S  = (double)sU[0] + 0.5 * (double)sU[1];
            double b  = (double)sU[2];
            double auc = ((2.0 * Nf + 1.0) * b + 1.0 - 2.0 * S) / (2.0 * Nf * D)
                       + 1.0 - (b + 1.0) / D;
            double sim = simf / (double)FRAMES;
            double nss = nssf / (double)FRAMES;
            double loss = auc + sim + nss;
            out[0] = (float)loss;
            out[1] = (float)auc;
            out[2] = (float)sim;
            out[3] = (float)nss;
        }
    }

    // ---- self-clean device state for the next graph replay ----
    __syncthreads();
    {
        uint4* hf4w = reinterpret_cast<uint4*>(g_hf) + t * (SPAN / 4);
        uint4* hn4w = reinterpret_cast<uint4*>(g_hn) + t * (SPAN / 4);
        uint4 z = make_uint4(0, 0, 0, 0);
        #pragma unroll
        for (int i = 0; i < SPAN / 4; i++) { hf4w[i] = z; hn4w[i] = z; }
        unsigned long long* s8 = reinterpret_cast<unsigned long long*>(&g_s);
        int n8 = (int)(sizeof(Stats) / 8);
        if (t < n8) s8[t] = 0ull;
        if (t == 0) {
            char* sc8 = reinterpret_cast<char*>(&g_s);
            for (int i = n8 * 8; i < (int)sizeof(Stats); i++) sc8[i] = 0;
            g_ticket1 = 0u;
        }
    }
}

extern "C" void kernel_launch(void* const* d_in, const int* in_sizes, int n_in,
                              void* d_out, int out_size) {
    const float* pred = (const float*)d_in[0];
    const float* gt   = (const float*)d_in[1];
    const int*   fix  = (const int*)d_in[2];
    float* out = (float*)d_out;

    dim3 gmain(TPF, FRAMES);            // 1440 blocks, 5 tiles each
    k_main<<<gmain, TPB>>>(pred, gt, fix);
    k_sim<<<NSIM_TOTAL, TPB>>>(pred, gt, fix);   // 45 hist blocks FIRST + 7200 SIM
    k_auc<<<1, TPB>>>(out);
}